// round 8
// baseline (speedup 1.0000x reference)
#include <cuda_runtime.h>
#include <cuda_fp16.h>
#include <cstdint>

// Problem shape (fixed by the dataset)
#define MM 4096
#define KK 4096
#define NN 8192

// ---------------- GEMM tiling (transposed: D[N,M] = Wc[N,K/2]sp x X[K,M]) ----
#define TN 128            // CTA tile over N (mma "M" dim)
#define TM 256            // CTA tile over M (mma "N" dim)
#define BK 64             // real k per stage (2 mma.sp slices of k=32)
#define STAGES 5
#define LDW 40            // Wc smem row stride in halves (32 + 8 pad)
#define WCB (TN * LDW * 2)        // 10240 B
#define XB  (TM * 128)            // 32768 B (XOR-swizzled 128B rows)
#define ECB 1024                  // metadata: 4 k-halves x 64 u32
#define STB (WCB + XB + ECB)      // 44032 B
#define SMEM_TOTAL (STAGES * STB) // 220160 B
#define KT (KK / BK)              // 64 k-iterations

// Scratch (module-scope device arrays — allowed):
__device__ __half   g_Wc[(size_t)NN * (KK / 2)];          // compressed W^T [N][K/2], 32MB
__device__ uint32_t g_Ec[(size_t)(KK / 16) * (NN / 2)];   // paired metadata, 4MB
__device__ __half   g_X[(size_t)MM * KK];                 // x fp16 [M][K], 32MB

// ---------------- PTX helpers ----------------
__device__ __forceinline__ void cp16(uint32_t dst, const void* src) {
    asm volatile("cp.async.cg.shared.global [%0], [%1], 16;" :: "r"(dst), "l"(src));
}
__device__ __forceinline__ void cp_commit() { asm volatile("cp.async.commit_group;"); }
template <int N> __device__ __forceinline__ void cp_wait() {
    asm volatile("cp.async.wait_group %0;" :: "n"(N));
}
__device__ __forceinline__ void ldsm_x4(uint32_t* r, uint32_t addr) {
    asm volatile("ldmatrix.sync.aligned.m8n8.x4.shared.b16 {%0,%1,%2,%3}, [%4];"
                 : "=r"(r[0]), "=r"(r[1]), "=r"(r[2]), "=r"(r[3]) : "r"(addr));
}
// Sparse MMA: D(16x8) += A(16x32, 2:4 sparse, row) * B(32x8, col); metadata e, selector 0
__device__ __forceinline__ void mma_sp(float* c, const uint32_t* a, const uint32_t* b, uint32_t e) {
    asm volatile("mma.sp::ordered_metadata.sync.aligned.m16n8k32.row.col.f32.f16.f16.f32 "
                 "{%0,%1,%2,%3}, {%4,%5,%6,%7}, {%8,%9,%10,%11}, {%0,%1,%2,%3}, %12, 0x0;"
                 : "+f"(c[0]), "+f"(c[1]), "+f"(c[2]), "+f"(c[3])
                 : "r"(a[0]), "r"(a[1]), "r"(a[2]), "r"(a[3]),
                   "r"(b[0]), "r"(b[1]), "r"(b[2]), "r"(b[3]), "r"(e));
}

// ---------------------------------------------------------------------------
// Pass 0: convert x fp32 -> fp16 (values fp16-representable; lossless)
// ---------------------------------------------------------------------------
__global__ void convert_x_kernel(const float* __restrict__ x) {
    size_t i = ((size_t)blockIdx.x * blockDim.x + threadIdx.x) * 8;
    float4 f0 = *reinterpret_cast<const float4*>(x + i);
    float4 f1 = *reinterpret_cast<const float4*>(x + i + 4);
    __half h[8] = {__float2half_rn(f0.x), __float2half_rn(f0.y),
                   __float2half_rn(f0.z), __float2half_rn(f0.w),
                   __float2half_rn(f1.x), __float2half_rn(f1.y),
                   __float2half_rn(f1.z), __float2half_rn(f1.w)};
    *reinterpret_cast<uint4*>(g_X + i) = *reinterpret_cast<uint4*>(h);
}

// ---------------------------------------------------------------------------
// Pass 1 (v2, coalesced): compressed sparse weights + mma.sp metadata.
// Thread owns n-quads (nbase..nbase+3) and (nbase+8..nbase+11) x 16 k.
// All 4 candidate q rows are read as int4 over n (sector-perfect), then the
// 2 nonzeros per 4-group are picked with branch-free selects in registers.
// Patterns p0..p5 -> (0,1)(0,2)(0,3)(1,2)(1,3)(2,3) -> nibbles 4,8,12,9,13,14
// g_Ec[(k/16)][(n/16)*8 + n%8] = row n bits[0:16) | row n+8 bits[16:32)
// ---------------------------------------------------------------------------
__global__ void dequant_sp_kernel(const int* __restrict__ q,
                                  const int* __restrict__ meta,
                                  const float* __restrict__ scale) {
    const unsigned LUT = 0x00ED9C84u;
    const int t = threadIdx.x;
    const int k0 = blockIdx.x * 64;
    const int n0 = blockIdx.y * 512;
    const int kq = t >> 6;                  // 0..3 -> 16-k chunk
    const int np = t & 63;                  // 64 n-slots covering 512 n
    const int kb = k0 + kq * 16;
    const int nbase = n0 + (np >> 1) * 16 + (np & 1) * 4;   // low quad; high = +8

    float sl[4], sh[4];
#pragma unroll
    for (int j = 0; j < 4; j++) {
        sl[j] = scale[(size_t)(kb >> 7) * NN + nbase + j];
        sh[j] = scale[(size_t)(kb >> 7) * NN + nbase + 8 + j];
    }

    __half wl[4][8], wh[4][8];
    unsigned ecl[4] = {0, 0, 0, 0}, ech[4] = {0, 0, 0, 0};

#pragma unroll
    for (int g = 0; g < 4; g++) {
        const int k = kb + g * 4;
        const size_t mrow = (size_t)(k >> 2) * NN;
        int4 ml = *(const int4*)(meta + mrow + nbase);
        int4 mh = *(const int4*)(meta + mrow + nbase + 8);
        int ql[4][4], qh[4][4];             // [row 0..3][n-offset 0..3]
#pragma unroll
        for (int r = 0; r < 4; r++) {
            int4 a = *(const int4*)(q + (size_t)(k + r) * NN + nbase);
            int4 b = *(const int4*)(q + (size_t)(k + r) * NN + nbase + 8);
            ql[r][0] = a.x; ql[r][1] = a.y; ql[r][2] = a.z; ql[r][3] = a.w;
            qh[r][0] = b.x; qh[r][1] = b.y; qh[r][2] = b.z; qh[r][3] = b.w;
        }
        int mls[4] = {ml.x, ml.y, ml.z, ml.w};
        int mhs[4] = {mh.x, mh.y, mh.z, mh.w};
#pragma unroll
        for (int j = 0; j < 4; j++) {
            unsigned nbl = (LUT >> (mls[j] * 4)) & 0xFu;
            int a0 = nbl & 3, a1 = nbl >> 2;
            int v0 = (a0 == 0) ? ql[0][j] : ((a0 == 1) ? ql[1][j] : ql[2][j]);
            int v1 = (a1 == 1) ? ql[1][j] : ((a1 == 2) ? ql[2][j] : ql[3][j]);
            wl[j][2 * g]     = __float2half_rn((float)(v0 - 8) * sl[j]);
            wl[j][2 * g + 1] = __float2half_rn((float)(v1 - 8) * sl[j]);
            ecl[j] |= nbl << (4 * g);

            unsigned nbh = (LUT >> (mhs[j] * 4)) & 0xFu;
            int b0 = nbh & 3, b1 = nbh >> 2;
            int u0 = (b0 == 0) ? qh[0][j] : ((b0 == 1) ? qh[1][j] : qh[2][j]);
            int u1 = (b1 == 1) ? qh[1][j] : ((b1 == 2) ? qh[2][j] : qh[3][j]);
            wh[j][2 * g]     = __float2half_rn((float)(u0 - 8) * sh[j]);
            wh[j][2 * g + 1] = __float2half_rn((float)(u1 - 8) * sh[j]);
            ech[j] |= nbh << (4 * g);
        }
    }

#pragma unroll
    for (int j = 0; j < 4; j++) {
        *reinterpret_cast<uint4*>(g_Wc + (size_t)(nbase + j) * (KK / 2) + (kb >> 1))
            = *reinterpret_cast<uint4*>(wl[j]);
        *reinterpret_cast<uint4*>(g_Wc + (size_t)(nbase + 8 + j) * (KK / 2) + (kb >> 1))
            = *reinterpret_cast<uint4*>(wh[j]);
    }
    uint4 ev = make_uint4(ecl[0] | (ech[0] << 16), ecl[1] | (ech[1] << 16),
                          ecl[2] | (ech[2] << 16), ecl[3] | (ech[3] << 16));
    *reinterpret_cast<uint4*>(g_Ec + (size_t)(kb >> 4) * (NN / 2)
                              + (size_t)(nbase >> 4) * 8 + (np & 1) * 4) = ev;
}

// ---------------------------------------------------------------------------
// Pass 2: sparse tensor-core GEMM, transposed (UNCHANGED from R7-validated).
// ---------------------------------------------------------------------------
__global__ __launch_bounds__(256, 1) void gemm_sp(float* __restrict__ out) {
    extern __shared__ char smem[];
    const uint32_t sb = (uint32_t)__cvta_generic_to_shared(smem);
    const int tid = threadIdx.x;
    const int warp = tid >> 5;
    const int lane = tid & 31;
    const int wm = warp >> 2;            // 0..1 over n (64 rows each)
    const int wn = warp & 3;             // 0..3 over m (64 cols each)
    const int n0 = blockIdx.x * TN;
    const int m0 = blockIdx.y * TM;

    float acc[4][8][4];
#pragma unroll
    for (int i = 0; i < 4; i++)
#pragma unroll
        for (int j = 0; j < 8; j++)
#pragma unroll
            for (int v = 0; v < 4; v++) acc[i][j][v] = 0.0f;

    const uint32_t wc_off = ((uint32_t)(wm * 64 + (lane & 15)) * LDW + (lane >> 4) * 8) * 2;
    const int bp = lane >> 3;
    const int brr = lane & 7;
    const int eh = lane & 1;

    auto load_stage = [&](int kt, int s) {
        uint32_t base = sb + s * STB;
#pragma unroll
        for (int i = 0; i < 2; i++) {            // Wc: 512 chunks
            int c = tid + i * 256;
            int nr = c >> 2, cc = c & 3;
            cp16(base + (uint32_t)nr * (LDW * 2) + cc * 16,
                 g_Wc + (size_t)(n0 + nr) * (KK / 2) + kt * 32 + cc * 8);
        }
#pragma unroll
        for (int i = 0; i < 8; i++) {            // X: 2048 chunks, XOR swizzle
            int c = tid + i * 256;
            int m = c >> 3, cc = c & 7;
            cp16(base + WCB + (uint32_t)m * 128 + (((uint32_t)(cc ^ (m & 7))) << 4),
                 g_X + (size_t)(m0 + m) * KK + kt * 64 + cc * 8);
        }
        if (tid < 64) {                           // Ec: 64 chunks
            int kh = tid >> 4, cc = tid & 15;
            cp16(base + WCB + XB + (uint32_t)kh * 256 + cc * 16,
                 g_Ec + (size_t)(kt * 4 + kh) * (NN / 2) + (size_t)blockIdx.x * 64 + cc * 4);
        }
    };

    uint32_t af[2][4][4];
    uint32_t ef[2][4];
    auto ldAE = [&](int buf, int s, int ks) {
        uint32_t base = sb + s * STB;
#pragma unroll
        for (int mi = 0; mi < 4; mi++)
            ldsm_x4(af[buf][mi], base + wc_off + ((uint32_t)(mi * 16) * LDW + ks * 16) * 2);
        const uint32_t* Ecs = reinterpret_cast<const uint32_t*>(smem + s * STB + WCB + XB);
#pragma unroll
        for (int mi = 0; mi < 4; mi++)
            ef[buf][mi] = Ecs[(2 * ks + eh) * 64 + wm * 32 + mi * 8 + (lane >> 2)];
    };

    // Prologue (R6 invariant): 4 stage loads committed, wait<2> -> stages 0,1 in
    load_stage(0, 0); cp_commit();
    load_stage(1, 1); cp_commit();
    load_stage(2, 2); cp_commit();
    load_stage(3, 3); cp_commit();
    cp_wait<2>();
    __syncthreads();
    ldAE(0, 0, 0);

#pragma unroll 1
    for (int kt = 0; kt < KT; kt++) {
        const int s = kt % STAGES;
        const int sn = (kt + 1) % STAGES;
        const uint32_t xbase = sb + s * STB + WCB;

#pragma unroll
        for (int ks = 0; ks < 2; ks++) {
            const int cur = ks;
            if (ks == 0)           ldAE(1, s, 1);
            else if (kt + 1 < KT)  ldAE(0, sn, 0);

            uint32_t bf[8][4];
#pragma unroll
            for (int ni = 0; ni < 8; ni++) {
                int m = wn * 64 + ni * 8 + brr;
                ldsm_x4(bf[ni], xbase + (uint32_t)m * 128 +
                                (((uint32_t)((ks * 4 + bp) ^ (m & 7))) << 4));
            }
#pragma unroll
            for (int mi = 0; mi < 4; mi++)
#pragma unroll
                for (int ni = 0; ni < 8; ni++)
                    mma_sp(acc[mi][ni], af[cur][mi], bf[ni], ef[cur][mi]);
        }

        if (kt + 4 < KT) load_stage(kt + 4, (kt + 4) % STAGES);
        cp_commit();
        cp_wait<2>();
        __syncthreads();
    }

    // Epilogue: transpose via smem (D[n][m] -> out[m][n]), coalesced stores
    float* D_s = reinterpret_cast<float*>(smem);    // 256 x 132 floats
#pragma unroll
    for (int mi = 0; mi < 4; mi++) {
#pragma unroll
        for (int ni = 0; ni < 8; ni++) {
            int ml = wn * 64 + ni * 8 + (lane & 3) * 2;
            int nl = wm * 64 + mi * 16 + (lane >> 2);
            D_s[(size_t)ml * 132 + nl]           = acc[mi][ni][0];
            D_s[(size_t)(ml + 1) * 132 + nl]     = acc[mi][ni][1];
            D_s[(size_t)ml * 132 + nl + 8]       = acc[mi][ni][2];
            D_s[(size_t)(ml + 1) * 132 + nl + 8] = acc[mi][ni][3];
        }
    }
    __syncthreads();
#pragma unroll 4
    for (int i = 0; i < 32; i++) {
        int m = warp * 32 + i;
        float4 v = *reinterpret_cast<const float4*>(&D_s[(size_t)m * 132 + lane * 4]);
        *reinterpret_cast<float4*>(out + (size_t)(m0 + m) * NN + n0 + lane * 4) = v;
    }
}

// ---------------------------------------------------------------------------
// Launch. Inputs per metadata order: x (f32), qweight (i32), meta (i32),
// scale (f32). Output: f32 [M, N].
// ---------------------------------------------------------------------------
extern "C" void kernel_launch(void* const* d_in, const int* in_sizes, int n_in,
                              void* d_out, int out_size) {
    (void)in_sizes; (void)n_in; (void)out_size;
    const float* x     = (const float*)d_in[0];
    const int*   qw    = (const int*)d_in[1];
    const int*   meta  = (const int*)d_in[2];
    const float* scale = (const float*)d_in[3];
    float*       out   = (float*)d_out;

    cudaFuncSetAttribute(gemm_sp, cudaFuncAttributeMaxDynamicSharedMemorySize, SMEM_TOTAL);

    convert_x_kernel<<<(MM * (KK / 8)) / 256, 256>>>(x);

    dim3 dq_grid(KK / 64, NN / 512);     // (64, 16)
    dequant_sp_kernel<<<dq_grid, 256>>>(qw, meta, scale);

    dim3 grid(NN / TN, MM / TM);         // (64, 16), n-block fastest
    gemm_sp<<<grid, 256, SMEM_TOTAL>>>(out);
}

// round 9
// speedup vs baseline: 1.0708x; 1.0708x over previous
#include <cuda_runtime.h>
#include <cuda_fp16.h>
#include <cstdint>

// Problem shape (fixed by the dataset)
#define MM 4096
#define KK 4096
#define NN 8192

// ---------------- GEMM tiling (transposed: D[N,M] = Wc[N,K/2]sp x X[K,M]) ----
#define TN 128            // CTA tile over N (mma "M" dim)
#define TM 128            // CTA tile over M (mma "N" dim)
#define BK 64             // real k per stage (2 mma.sp slices of k=32)
#define STAGES 4
#define LDW 40            // Wc smem row stride in halves (32 + 8 pad)
#define WCB (TN * LDW * 2)        // 10240 B
#define XB  (TM * 128)            // 16384 B (XOR-swizzled 128B rows)
#define ECB 1024                  // metadata: 4 k-halves x 64 u32
#define STB (WCB + XB + ECB)      // 27648 B
#define SMEM_TOTAL (STAGES * STB) // 110592 B -> 2 CTAs/SM
#define KT (KK / BK)              // 64 k-iterations

// Scratch (module-scope device arrays — allowed):
__device__ __half   g_Wc[(size_t)NN * (KK / 2)];          // compressed W^T [N][K/2], 32MB
__device__ uint32_t g_Ec[(size_t)(KK / 16) * (NN / 2)];   // paired metadata, 4MB
__device__ __half   g_X[(size_t)MM * KK];                 // x fp16 [M][K], 32MB

// ---------------- PTX helpers ----------------
__device__ __forceinline__ void cp16(uint32_t dst, const void* src) {
    asm volatile("cp.async.cg.shared.global [%0], [%1], 16;" :: "r"(dst), "l"(src));
}
__device__ __forceinline__ void cp_commit() { asm volatile("cp.async.commit_group;"); }
template <int N> __device__ __forceinline__ void cp_wait() {
    asm volatile("cp.async.wait_group %0;" :: "n"(N));
}
__device__ __forceinline__ void ldsm_x4(uint32_t* r, uint32_t addr) {
    asm volatile("ldmatrix.sync.aligned.m8n8.x4.shared.b16 {%0,%1,%2,%3}, [%4];"
                 : "=r"(r[0]), "=r"(r[1]), "=r"(r[2]), "=r"(r[3]) : "r"(addr));
}
// Sparse MMA: D(16x8) += A(16x32, 2:4 sparse, row) * B(32x8, col); metadata e, selector 0
__device__ __forceinline__ void mma_sp(float* c, const uint32_t* a, const uint32_t* b, uint32_t e) {
    asm volatile("mma.sp::ordered_metadata.sync.aligned.m16n8k32.row.col.f32.f16.f16.f32 "
                 "{%0,%1,%2,%3}, {%4,%5,%6,%7}, {%8,%9,%10,%11}, {%0,%1,%2,%3}, %12, 0x0;"
                 : "+f"(c[0]), "+f"(c[1]), "+f"(c[2]), "+f"(c[3])
                 : "r"(a[0]), "r"(a[1]), "r"(a[2]), "r"(a[3]),
                   "r"(b[0]), "r"(b[1]), "r"(b[2]), "r"(b[3]), "r"(e));
}

// ---------------------------------------------------------------------------
// Pass 0: convert x fp32 -> fp16 (values fp16-representable; lossless)
// ---------------------------------------------------------------------------
__global__ void convert_x_kernel(const float* __restrict__ x) {
    size_t i = ((size_t)blockIdx.x * blockDim.x + threadIdx.x) * 8;
    float4 f0 = *reinterpret_cast<const float4*>(x + i);
    float4 f1 = *reinterpret_cast<const float4*>(x + i + 4);
    __half h[8] = {__float2half_rn(f0.x), __float2half_rn(f0.y),
                   __float2half_rn(f0.z), __float2half_rn(f0.w),
                   __float2half_rn(f1.x), __float2half_rn(f1.y),
                   __float2half_rn(f1.z), __float2half_rn(f1.w)};
    *reinterpret_cast<uint4*>(g_X + i) = *reinterpret_cast<uint4*>(h);
}

// ---------------------------------------------------------------------------
// Pass 1 (R7-proven version): compressed sparse weights + mma.sp metadata.
// For each (n, k-group of 4): pattern p gives nonzero positions (i0 < i1).
// Compressed value j = (q[4g+ij][n] - 8) * scale;  metadata nibble = i0 | i1<<2.
// Patterns p0..p5 -> (0,1)(0,2)(0,3)(1,2)(1,3)(2,3) -> nibbles 4,8,12,9,13,14
// g_Ec[(k/16)][(n/16)*8 + n%8] = row n bits[0:16) | row n+8 bits[16:32)
// ---------------------------------------------------------------------------
__global__ void dequant_sp_kernel(const int* __restrict__ q,
                                  const int* __restrict__ meta,
                                  const float* __restrict__ scale) {
    const unsigned LUT = 0x00ED9C84u;   // nibble per pattern, 4 bits each
    int t = threadIdx.x;
    int k0 = blockIdx.x * 64;
    int n0 = blockIdx.y * 128;
    int kq = t >> 6;                    // 0..3 -> 16-k chunk
    int np = t & 63;                    // n-pair index
    int n  = n0 + (np >> 3) * 16 + (np & 7);
    int kb = k0 + kq * 16;
    float s1 = scale[(size_t)(kb >> 7) * NN + n];
    float s2 = scale[(size_t)(kb >> 7) * NN + n + 8];

    __half w1[8], w2[8];
    unsigned ec = 0;
#pragma unroll
    for (int g = 0; g < 4; g++) {
        int k = kb + g * 4;
        size_t mrow = (size_t)(k >> 2) * NN;
        unsigned nb1 = (LUT >> (meta[mrow + n] * 4)) & 0xFu;
        unsigned nb2 = (LUT >> (meta[mrow + n + 8] * 4)) & 0xFu;
        int a0 = nb1 & 3, a1 = nb1 >> 2;
        int b0 = nb2 & 3, b1 = nb2 >> 2;
        w1[2 * g]     = __float2half_rn((float)(q[(size_t)(k + a0) * NN + n] - 8) * s1);
        w1[2 * g + 1] = __float2half_rn((float)(q[(size_t)(k + a1) * NN + n] - 8) * s1);
        w2[2 * g]     = __float2half_rn((float)(q[(size_t)(k + b0) * NN + n + 8] - 8) * s2);
        w2[2 * g + 1] = __float2half_rn((float)(q[(size_t)(k + b1) * NN + n + 8] - 8) * s2);
        ec |= nb1 << (4 * g);
        ec |= nb2 << (16 + 4 * g);
    }
    *reinterpret_cast<uint4*>(g_Wc + (size_t)n * (KK / 2) + (kb >> 1)) = *reinterpret_cast<uint4*>(w1);
    *reinterpret_cast<uint4*>(g_Wc + (size_t)(n + 8) * (KK / 2) + (kb >> 1)) = *reinterpret_cast<uint4*>(w2);
    g_Ec[(size_t)(kb >> 4) * (NN / 2) + (size_t)(n >> 4) * 8 + (n & 7)] = ec;
}

// ---------------------------------------------------------------------------
// Pass 2: sparse tensor-core GEMM, transposed, occupancy 2.
// 8 warps (wm x wn = 2 x 4), warp tile 64n x 32m, acc = 64 regs.
// 4-stage cp.async ring; no fragment cross-buffering (occ=2 hides latency).
// Residency invariant: entering iter kt, stage kt resident (prologue: 3
// commits + wait<2>; steady: commit-per-iter + wait<2> -> stage kt+1 done).
// ---------------------------------------------------------------------------
__global__ __launch_bounds__(256, 2) void gemm_sp(float* __restrict__ out) {
    extern __shared__ char smem[];
    const uint32_t sb = (uint32_t)__cvta_generic_to_shared(smem);
    const int tid = threadIdx.x;
    const int warp = tid >> 5;
    const int lane = tid & 31;
    const int wm = warp >> 2;            // 0..1 over n (64 rows each)
    const int wn = warp & 3;             // 0..3 over m (32 cols each)
    const int n0 = blockIdx.x * TN;
    const int m0 = blockIdx.y * TM;

    float acc[4][4][4];
#pragma unroll
    for (int i = 0; i < 4; i++)
#pragma unroll
        for (int j = 0; j < 4; j++)
#pragma unroll
            for (int v = 0; v < 4; v++) acc[i][j][v] = 0.0f;

    const uint32_t wc_off = ((uint32_t)(wm * 64 + (lane & 15)) * LDW + (lane >> 4) * 8) * 2;
    const int bp = lane >> 3;            // B ldmatrix: k-piece 0..3
    const int brr = lane & 7;            // row within 8 m
    const int eh = lane & 1;             // metadata k-half

    auto load_stage = [&](int kt, int s) {
        uint32_t base = sb + s * STB;
#pragma unroll
        for (int i = 0; i < 2; i++) {            // Wc: 512 chunks
            int c = tid + i * 256;
            int nr = c >> 2, cc = c & 3;
            cp16(base + (uint32_t)nr * (LDW * 2) + cc * 16,
                 g_Wc + (size_t)(n0 + nr) * (KK / 2) + kt * 32 + cc * 8);
        }
#pragma unroll
        for (int i = 0; i < 4; i++) {            // X: 1024 chunks, XOR swizzle
            int c = tid + i * 256;
            int m = c >> 3, cc = c & 7;
            cp16(base + WCB + (uint32_t)m * 128 + (((uint32_t)(cc ^ (m & 7))) << 4),
                 g_X + (size_t)(m0 + m) * KK + kt * 64 + cc * 8);
        }
        if (tid < 64) {                           // Ec: 64 chunks
            int kh = tid >> 4, cc = tid & 15;
            cp16(base + WCB + XB + (uint32_t)kh * 256 + cc * 16,
                 g_Ec + (size_t)(kt * 4 + kh) * (NN / 2) + (size_t)blockIdx.x * 64 + cc * 4);
        }
    };

    // Prologue: 3 stage loads committed; wait<2> -> stage 0 resident
    load_stage(0, 0); cp_commit();
    load_stage(1, 1); cp_commit();
    load_stage(2, 2); cp_commit();
    cp_wait<2>();
    __syncthreads();

#pragma unroll 1
    for (int kt = 0; kt < KT; kt++) {
        const int s = kt % STAGES;
        const uint32_t base = sb + s * STB;
        const uint32_t xbase = base + WCB;
        const uint32_t* Ecs = reinterpret_cast<const uint32_t*>(smem + s * STB + WCB + XB);

#pragma unroll
        for (int ks = 0; ks < 2; ks++) {
            uint32_t af[4][4], ef[4], bf[4][4];
#pragma unroll
            for (int mi = 0; mi < 4; mi++)
                ldsm_x4(af[mi], base + wc_off + ((uint32_t)(mi * 16) * LDW + ks * 16) * 2);
#pragma unroll
            for (int ni = 0; ni < 4; ni++) {
                int m = wn * 32 + ni * 8 + brr;
                ldsm_x4(bf[ni], xbase + (uint32_t)m * 128 +
                                (((uint32_t)((ks * 4 + bp) ^ (m & 7))) << 4));
            }
#pragma unroll
            for (int mi = 0; mi < 4; mi++)
                ef[mi] = Ecs[(2 * ks + eh) * 64 + wm * 32 + mi * 8 + (lane >> 2)];
#pragma unroll
            for (int mi = 0; mi < 4; mi++)
#pragma unroll
                for (int ni = 0; ni < 4; ni++)
                    mma_sp(acc[mi][ni], af[mi], bf[ni], ef[mi]);
        }

        // Refill stage (kt+3)%4 = (kt-1)%4: read-complete as of end of iter
        // kt-1 (ordered by that iteration's barrier).
        if (kt + 3 < KT) load_stage(kt + 3, (kt + 3) % STAGES);
        cp_commit();
        cp_wait<2>();                // stage kt+1 resident for next iter
        __syncthreads();
    }

    // Epilogue: transpose via smem (D[n][m] -> out[m][n]), coalesced stores
    float* D_s = reinterpret_cast<float*>(smem);    // 128 x 132 floats = 67.5KB
#pragma unroll
    for (int mi = 0; mi < 4; mi++) {
#pragma unroll
        for (int ni = 0; ni < 4; ni++) {
            int ml = wn * 32 + ni * 8 + (lane & 3) * 2;
            int nl = wm * 64 + mi * 16 + (lane >> 2);
            D_s[(size_t)ml * 132 + nl]           = acc[mi][ni][0];
            D_s[(size_t)(ml + 1) * 132 + nl]     = acc[mi][ni][1];
            D_s[(size_t)ml * 132 + nl + 8]       = acc[mi][ni][2];
            D_s[(size_t)(ml + 1) * 132 + nl + 8] = acc[mi][ni][3];
        }
    }
    __syncthreads();
#pragma unroll 4
    for (int i = 0; i < 16; i++) {
        int m = warp * 16 + i;
        float4 v = *reinterpret_cast<const float4*>(&D_s[(size_t)m * 132 + lane * 4]);
        *reinterpret_cast<float4*>(out + (size_t)(m0 + m) * NN + n0 + lane * 4) = v;
    }
}

// ---------------------------------------------------------------------------
// Launch. Inputs per metadata order: x (f32), qweight (i32), meta (i32),
// scale (f32). Output: f32 [M, N].
// ---------------------------------------------------------------------------
extern "C" void kernel_launch(void* const* d_in, const int* in_sizes, int n_in,
                              void* d_out, int out_size) {
    (void)in_sizes; (void)n_in; (void)out_size;
    const float* x     = (const float*)d_in[0];
    const int*   qw    = (const int*)d_in[1];
    const int*   meta  = (const int*)d_in[2];
    const float* scale = (const float*)d_in[3];
    float*       out   = (float*)d_out;

    cudaFuncSetAttribute(gemm_sp, cudaFuncAttributeMaxDynamicSharedMemorySize, SMEM_TOTAL);

    convert_x_kernel<<<(MM * (KK / 8)) / 256, 256>>>(x);

    dim3 dq_grid(KK / 64, NN / 128);     // (64, 64)
    dequant_sp_kernel<<<dq_grid, 256>>>(qw, meta, scale);

    dim3 grid(NN / TN, MM / TM);         // (64, 32), n-block fastest
    gemm_sp<<<grid, 256, SMEM_TOTAL>>>(out);
}

// round 10
// speedup vs baseline: 1.1691x; 1.0919x over previous
#include <cuda_runtime.h>
#include <cuda_fp16.h>
#include <cstdint>

// Problem shape (fixed by the dataset)
#define MM 4096
#define KK 4096
#define NN 8192

// ---------------- GEMM tiling (transposed: D[N,M] = Wc[N,K/2]sp x X[K,M]) ----
#define TN 128            // CTA tile over N (mma "M" dim)
#define TM 128            // CTA tile over M (mma "N" dim)
#define BK 64             // real k per stage (2 mma.sp slices of k=32)
#define STAGES 4
#define LDW 40            // Wc smem row stride in halves (32 + 8 pad)
#define WCB (TN * LDW * 2)        // 10240 B
#define XB  (TM * 128)            // 16384 B (XOR-swizzled 128B rows)
#define ECB 1024                  // metadata: 4 k-halves x 64 u32
#define STB (WCB + XB + ECB)      // 27648 B
#define SMEM_TOTAL (STAGES * STB) // 110592 B -> 2 CTAs/SM
#define KT (KK / BK)              // 64 k-iterations

// Scratch (module-scope device arrays — allowed):
__device__ __half   g_Wc[(size_t)NN * (KK / 2)];          // compressed W^T [N][K/2], 32MB
__device__ uint32_t g_Ec[(size_t)(KK / 16) * (NN / 2)];   // paired metadata, 4MB
__device__ __half   g_X[(size_t)MM * KK];                 // x fp16 [M][K], 32MB

// ---------------- PTX helpers ----------------
__device__ __forceinline__ void cp16(uint32_t dst, const void* src) {
    asm volatile("cp.async.cg.shared.global [%0], [%1], 16;" :: "r"(dst), "l"(src));
}
__device__ __forceinline__ void cp_commit() { asm volatile("cp.async.commit_group;"); }
template <int N> __device__ __forceinline__ void cp_wait() {
    asm volatile("cp.async.wait_group %0;" :: "n"(N));
}
__device__ __forceinline__ void ldsm_x4(uint32_t* r, uint32_t addr) {
    asm volatile("ldmatrix.sync.aligned.m8n8.x4.shared.b16 {%0,%1,%2,%3}, [%4];"
                 : "=r"(r[0]), "=r"(r[1]), "=r"(r[2]), "=r"(r[3]) : "r"(addr));
}
// Sparse MMA: D(16x8) += A(16x32, 2:4 sparse, row) * B(32x8, col); metadata e, selector 0
__device__ __forceinline__ void mma_sp(float* c, const uint32_t* a, const uint32_t* b, uint32_t e) {
    asm volatile("mma.sp::ordered_metadata.sync.aligned.m16n8k32.row.col.f32.f16.f16.f32 "
                 "{%0,%1,%2,%3}, {%4,%5,%6,%7}, {%8,%9,%10,%11}, {%0,%1,%2,%3}, %12, 0x0;"
                 : "+f"(c[0]), "+f"(c[1]), "+f"(c[2]), "+f"(c[3])
                 : "r"(a[0]), "r"(a[1]), "r"(a[2]), "r"(a[3]),
                   "r"(b[0]), "r"(b[1]), "r"(b[2]), "r"(b[3]), "r"(e));
}

// ---------------------------------------------------------------------------
// Pass 0: convert x fp32 -> fp16 (values fp16-representable; lossless)
// ---------------------------------------------------------------------------
__global__ void convert_x_kernel(const float* __restrict__ x) {
    size_t i = ((size_t)blockIdx.x * blockDim.x + threadIdx.x) * 8;
    float4 f0 = *reinterpret_cast<const float4*>(x + i);
    float4 f1 = *reinterpret_cast<const float4*>(x + i + 4);
    __half h[8] = {__float2half_rn(f0.x), __float2half_rn(f0.y),
                   __float2half_rn(f0.z), __float2half_rn(f0.w),
                   __float2half_rn(f1.x), __float2half_rn(f1.y),
                   __float2half_rn(f1.z), __float2half_rn(f1.w)};
    *reinterpret_cast<uint4*>(g_X + i) = *reinterpret_cast<uint4*>(h);
}

// ---------------------------------------------------------------------------
// Pass 1 (R7-proven version): compressed sparse weights + mma.sp metadata.
// Patterns p0..p5 -> (0,1)(0,2)(0,3)(1,2)(1,3)(2,3) -> nibbles 4,8,12,9,13,14
// g_Ec[(k/16)][(n/16)*8 + n%8] = row n bits[0:16) | row n+8 bits[16:32)
// ---------------------------------------------------------------------------
__global__ void dequant_sp_kernel(const int* __restrict__ q,
                                  const int* __restrict__ meta,
                                  const float* __restrict__ scale) {
    const unsigned LUT = 0x00ED9C84u;   // nibble per pattern, 4 bits each
    int t = threadIdx.x;
    int k0 = blockIdx.x * 64;
    int n0 = blockIdx.y * 128;
    int kq = t >> 6;                    // 0..3 -> 16-k chunk
    int np = t & 63;                    // n-pair index
    int n  = n0 + (np >> 3) * 16 + (np & 7);
    int kb = k0 + kq * 16;
    float s1 = scale[(size_t)(kb >> 7) * NN + n];
    float s2 = scale[(size_t)(kb >> 7) * NN + n + 8];

    __half w1[8], w2[8];
    unsigned ec = 0;
#pragma unroll
    for (int g = 0; g < 4; g++) {
        int k = kb + g * 4;
        size_t mrow = (size_t)(k >> 2) * NN;
        unsigned nb1 = (LUT >> (meta[mrow + n] * 4)) & 0xFu;
        unsigned nb2 = (LUT >> (meta[mrow + n + 8] * 4)) & 0xFu;
        int a0 = nb1 & 3, a1 = nb1 >> 2;
        int b0 = nb2 & 3, b1 = nb2 >> 2;
        w1[2 * g]     = __float2half_rn((float)(q[(size_t)(k + a0) * NN + n] - 8) * s1);
        w1[2 * g + 1] = __float2half_rn((float)(q[(size_t)(k + a1) * NN + n] - 8) * s1);
        w2[2 * g]     = __float2half_rn((float)(q[(size_t)(k + b0) * NN + n + 8] - 8) * s2);
        w2[2 * g + 1] = __float2half_rn((float)(q[(size_t)(k + b1) * NN + n + 8] - 8) * s2);
        ec |= nb1 << (4 * g);
        ec |= nb2 << (16 + 4 * g);
    }
    *reinterpret_cast<uint4*>(g_Wc + (size_t)n * (KK / 2) + (kb >> 1)) = *reinterpret_cast<uint4*>(w1);
    *reinterpret_cast<uint4*>(g_Wc + (size_t)(n + 8) * (KK / 2) + (kb >> 1)) = *reinterpret_cast<uint4*>(w2);
    g_Ec[(size_t)(kb >> 4) * (NN / 2) + (size_t)(n >> 4) * 8 + (n & 7)] = ec;
}

// ---------------------------------------------------------------------------
// Pass 2: sparse tensor-core GEMM, transposed, occupancy 2, 4 warps (2x2),
// warp tile 64n x 64m -> minimal LDSM redundancy (A 2x, B 2x).
// 4-stage cp.async ring, R6-proven residency invariant.
// ---------------------------------------------------------------------------
__global__ __launch_bounds__(128, 2) void gemm_sp(float* __restrict__ out) {
    extern __shared__ char smem[];
    const uint32_t sb = (uint32_t)__cvta_generic_to_shared(smem);
    const int tid = threadIdx.x;
    const int warp = tid >> 5;
    const int lane = tid & 31;
    const int wm = warp >> 1;            // 0..1 over n (64 rows each)
    const int wn = warp & 1;             // 0..1 over m (64 cols each)
    const int n0 = blockIdx.x * TN;
    const int m0 = blockIdx.y * TM;

    float acc[4][8][4];
#pragma unroll
    for (int i = 0; i < 4; i++)
#pragma unroll
        for (int j = 0; j < 8; j++)
#pragma unroll
            for (int v = 0; v < 4; v++) acc[i][j][v] = 0.0f;

    const uint32_t wc_off = ((uint32_t)(wm * 64 + (lane & 15)) * LDW + (lane >> 4) * 8) * 2;
    const int bp = lane >> 3;            // B ldmatrix: k-piece 0..3
    const int brr = lane & 7;            // row within 8 m
    const int eh = lane & 1;             // metadata k-half

    auto load_stage = [&](int kt, int s) {
        uint32_t base = sb + s * STB;
#pragma unroll
        for (int i = 0; i < 4; i++) {            // Wc: 512 chunks of 16B
            int c = tid + i * 128;
            int nr = c >> 2, cc = c & 3;
            cp16(base + (uint32_t)nr * (LDW * 2) + cc * 16,
                 g_Wc + (size_t)(n0 + nr) * (KK / 2) + kt * 32 + cc * 8);
        }
#pragma unroll
        for (int i = 0; i < 8; i++) {            // X: 1024 chunks, XOR swizzle
            int c = tid + i * 128;
            int m = c >> 3, cc = c & 7;
            cp16(base + WCB + (uint32_t)m * 128 + (((uint32_t)(cc ^ (m & 7))) << 4),
                 g_X + (size_t)(m0 + m) * KK + kt * 64 + cc * 8);
        }
        if (tid < 64) {                           // Ec: 64 chunks
            int kh = tid >> 4, cc = tid & 15;
            cp16(base + WCB + XB + (uint32_t)kh * 256 + cc * 16,
                 g_Ec + (size_t)(kt * 4 + kh) * (NN / 2) + (size_t)blockIdx.x * 64 + cc * 4);
        }
    };

    // Prologue: 3 stage loads committed; wait<2> -> stage 0 resident
    load_stage(0, 0); cp_commit();
    load_stage(1, 1); cp_commit();
    load_stage(2, 2); cp_commit();
    cp_wait<2>();
    __syncthreads();

#pragma unroll 1
    for (int kt = 0; kt < KT; kt++) {
        const int s = kt % STAGES;
        const uint32_t base = sb + s * STB;
        const uint32_t xbase = base + WCB;
        const uint32_t* Ecs = reinterpret_cast<const uint32_t*>(smem + s * STB + WCB + XB);

#pragma unroll
        for (int ks = 0; ks < 2; ks++) {
            uint32_t af[4][4], ef[4], bf[8][4];
#pragma unroll
            for (int mi = 0; mi < 4; mi++)
                ldsm_x4(af[mi], base + wc_off + ((uint32_t)(mi * 16) * LDW + ks * 16) * 2);
#pragma unroll
            for (int ni = 0; ni < 8; ni++) {
                int m = wn * 64 + ni * 8 + brr;
                ldsm_x4(bf[ni], xbase + (uint32_t)m * 128 +
                                (((uint32_t)((ks * 4 + bp) ^ (m & 7))) << 4));
            }
#pragma unroll
            for (int mi = 0; mi < 4; mi++)
                ef[mi] = Ecs[(2 * ks + eh) * 64 + wm * 32 + mi * 8 + (lane >> 2)];
#pragma unroll
            for (int mi = 0; mi < 4; mi++)
#pragma unroll
                for (int ni = 0; ni < 8; ni++)
                    mma_sp(acc[mi][ni], af[mi], bf[ni], ef[mi]);
        }

        // Refill stage (kt+3)%4 = (kt-1)%4: read-complete as of end of iter
        // kt-1 (ordered by that iteration's barrier).
        if (kt + 3 < KT) load_stage(kt + 3, (kt + 3) % STAGES);
        cp_commit();
        cp_wait<2>();                // stage kt+1 resident for next iter
        __syncthreads();
    }

    // Epilogue: transpose via smem (D[n][m] -> out[m][n]), coalesced stores
    float* D_s = reinterpret_cast<float*>(smem);    // 128 x 132 floats = 67.5KB
#pragma unroll
    for (int mi = 0; mi < 4; mi++) {
#pragma unroll
        for (int ni = 0; ni < 8; ni++) {
            int ml = wn * 64 + ni * 8 + (lane & 3) * 2;
            int nl = wm * 64 + mi * 16 + (lane >> 2);
            D_s[(size_t)ml * 132 + nl]           = acc[mi][ni][0];
            D_s[(size_t)(ml + 1) * 132 + nl]     = acc[mi][ni][1];
            D_s[(size_t)ml * 132 + nl + 8]       = acc[mi][ni][2];
            D_s[(size_t)(ml + 1) * 132 + nl + 8] = acc[mi][ni][3];
        }
    }
    __syncthreads();
#pragma unroll 4
    for (int i = 0; i < 32; i++) {
        int m = warp * 32 + i;
        float4 v = *reinterpret_cast<const float4*>(&D_s[(size_t)m * 132 + lane * 4]);
        *reinterpret_cast<float4*>(out + (size_t)(m0 + m) * NN + n0 + lane * 4) = v;
    }
}

// ---------------------------------------------------------------------------
// Launch. Inputs per metadata order: x (f32), qweight (i32), meta (i32),
// scale (f32). Output: f32 [M, N].
// ---------------------------------------------------------------------------
extern "C" void kernel_launch(void* const* d_in, const int* in_sizes, int n_in,
                              void* d_out, int out_size) {
    (void)in_sizes; (void)n_in; (void)out_size;
    const float* x     = (const float*)d_in[0];
    const int*   qw    = (const int*)d_in[1];
    const int*   meta  = (const int*)d_in[2];
    const float* scale = (const float*)d_in[3];
    float*       out   = (float*)d_out;

    cudaFuncSetAttribute(gemm_sp, cudaFuncAttributeMaxDynamicSharedMemorySize, SMEM_TOTAL);

    convert_x_kernel<<<(MM * (KK / 8)) / 256, 256>>>(x);

    dim3 dq_grid(KK / 64, NN / 128);     // (64, 64)
    dequant_sp_kernel<<<dq_grid, 256>>>(qw, meta, scale);

    dim3 grid(NN / TN, MM / TM);         // (64, 32), n-block fastest
    gemm_sp<<<grid, 128, SMEM_TOTAL>>>(out);
}